// round 9
// baseline (speedup 1.0000x reference)
#include <cuda_runtime.h>
#include <math.h>

#define BN 64
#define SN 512
#define DN 768
#define HN 384
#define GN 1536
#define TN 22

#define NBLK_REC 128
#define REC_THREADS 256

// ---------------- scratch (static device globals; zero-initialized) ---------
__device__ float g_embeds[BN * SN * DN];
__device__ float g_xg[2 * SN * BN * GN];                 // [dir][t][b][4H]
__device__ float g_lstm[BN * SN * 2 * HN];               // [b][t][2H]
__device__ float g_h[2 * 2 * BN * HN];                   // [dir][parity][b][H]
__device__ int   g_n[BN];
__device__ int   g_sent[BN];
__device__ int   g_last[BN];
__device__ unsigned g_bcnt[8];                           // monotonic, per (bg,dir)
__device__ unsigned g_bgen[8];

// ---------------- packed fp32x2 / fast math helpers ---------------------------
__device__ __forceinline__ unsigned long long fma2(unsigned long long a,
                                                   unsigned long long b,
                                                   unsigned long long c) {
    unsigned long long d;
    asm("fma.rn.f32x2 %0, %1, %2, %3;" : "=l"(d) : "l"(a), "l"(b), "l"(c));
    return d;
}
__device__ __forceinline__ float unpack_sum(unsigned long long v) {
    float lo, hi;
    asm("mov.b64 {%0, %1}, %2;" : "=f"(lo), "=f"(hi) : "l"(v));
    return lo + hi;
}
__device__ __forceinline__ float tanh_fast(float x) {
    float y;
    asm("tanh.approx.f32 %0, %1;" : "=f"(y) : "f"(x));
    return y;
}
__device__ __forceinline__ float sig_fast(float x) {
    return 0.5f * tanh_fast(0.5f * x) + 0.5f;
}

// ---------------- scoped atomics for the grid barrier --------------------------
__device__ __forceinline__ unsigned atom_add_acqrel(unsigned* p, unsigned v) {
    unsigned old;
    asm volatile("atom.acq_rel.gpu.global.add.u32 %0, [%1], %2;"
                 : "=r"(old) : "l"(p), "r"(v) : "memory");
    return old;
}
__device__ __forceinline__ unsigned ld_acquire(unsigned* p) {
    unsigned v;
    asm volatile("ld.acquire.gpu.global.u32 %0, [%1];" : "=r"(v) : "l"(p) : "memory");
    return v;
}
__device__ __forceinline__ void st_release_u32(unsigned* p, unsigned v) {
    asm volatile("st.release.gpu.global.u32 [%0], %1;" :: "l"(p), "r"(v) : "memory");
}

// ---------------- index helpers -------------------------------------------------
__device__ __forceinline__ long long ld_idx(const void* p, int i, bool is64) {
    return is64 ? ((const long long*)p)[i] : (long long)((const int*)p)[i];
}
__device__ __forceinline__ bool detect_is64(const void* start_ids) {
    return ((const int*)start_ids)[1] == 0;
}

// ---------------- K0: per-batch metadata ----------------------------------------
__global__ void meta_kernel(const void* start_ids, const void* masks) {
    int b = blockIdx.x;
    int tid = threadIdx.x;
    bool is64 = detect_is64(start_ids);
    __shared__ int red[256];
    int cnt = 0, sm = 0;
    for (int t = tid; t < SN; t += 256) {
        long long sv = ld_idx(start_ids, b * SN + t, is64);
        long long mv = ld_idx(masks, b * SN + t, is64);
        cnt += (sv >= 0);
        sm += (int)mv;
    }
    red[tid] = cnt; __syncthreads();
    for (int o = 128; o > 0; o >>= 1) { if (tid < o) red[tid] += red[tid + o]; __syncthreads(); }
    int ntot = red[0]; __syncthreads();
    red[tid] = sm; __syncthreads();
    for (int o = 128; o > 0; o >>= 1) { if (tid < o) red[tid] += red[tid + o]; __syncthreads(); }
    int stot = red[0];
    if (tid == 0) {
        g_n[b] = ntot;
        g_sent[b] = stot;
        long long last = 0;
        if (ntot > 0) last = ld_idx(start_ids, b * SN + ntot - 1, is64);
        g_last[b] = (int)last;
    }
}

// ---------------- K1: align gather -----------------------------------------------
__global__ void gather_kernel(const float* __restrict__ hs, const void* __restrict__ start_ids) {
    int t = blockIdx.x, b = blockIdx.y;
    int sent = g_sent[b];
    if (t >= sent) return;
    bool is64 = detect_is64(start_ids);
    int n = g_n[b];
    long long idx;
    if (t == 0)      idx = 0;
    else if (t < n)  idx = ld_idx(start_ids, b * SN + t, is64) - 1;
    else if (t == n) idx = g_last[b];
    else             idx = 0;
    if (idx < 0) idx = 0;
    if (idx > SN - 1) idx = SN - 1;
    const float4* src = (const float4*)(hs + ((size_t)b * SN + (size_t)idx) * DN);
    float4* dst = (float4*)(g_embeds + ((size_t)b * SN + t) * DN);
    dst[threadIdx.x] = src[threadIdx.x];
}

// ---------------- K2: input projection GEMM (f32x2, cp.async, 2 blocks/SM) -------
__global__ void __launch_bounds__(256, 2) proj_kernel(
    const float* __restrict__ Wf, const float* __restrict__ Wb,
    const float* __restrict__ bihf, const float* __restrict__ bhhf,
    const float* __restrict__ bihb, const float* __restrict__ bhhb)
{
    int b = blockIdx.z & 63;
    int dir = blockIdx.z >> 6;
    int sent = g_sent[b];
    int t0 = blockIdx.y * 128;
    if (t0 >= sent) return;
    int n0 = blockIdx.x * 64;

    const float* W   = dir ? Wb   : Wf;
    const float* bih = dir ? bihb : bihf;
    const float* bhh = dir ? bhhb : bhhf;

    __shared__ float As[2][128][20];
    __shared__ float Bs[2][64][20];

    int tid = threadIdx.x;
    int tx = tid & 15, ty = tid >> 4;
    int bsw = ((tx >> 3) & 1) << 2;

    unsigned long long acc[8][4];
    #pragma unroll
    for (int i = 0; i < 8; i++)
        #pragma unroll
        for (int j = 0; j < 4; j++) acc[i][j] = 0ull;

    #define PROJ_FILL(stg, kt)                                                           \
        do {                                                                             \
            _Pragma("unroll")                                                            \
            for (int f = 0; f < 2; f++) {                                                \
                int lin = tid + f * 256;                                                 \
                int row = lin >> 2;                                                      \
                int c = (lin & 3) * 4;                                                   \
                unsigned sa = (unsigned)__cvta_generic_to_shared(&As[stg][row][c]);      \
                const float* ga = &g_embeds[((size_t)b * SN + t0 + row) * DN + (kt) + c];\
                asm volatile("cp.async.ca.shared.global [%0], [%1], 16;" :: "r"(sa), "l"(ga)); \
            }                                                                            \
            {                                                                            \
                int row = tid >> 2;                                                      \
                int c = (tid & 3) * 4;                                                   \
                int cs = c ^ (((row >> 3) & 1) << 2);                                    \
                unsigned sb = (unsigned)__cvta_generic_to_shared(&Bs[stg][row][cs]);     \
                const float* gb = &W[(size_t)(n0 + row) * DN + (kt) + c];                \
                asm volatile("cp.async.ca.shared.global [%0], [%1], 16;" :: "r"(sb), "l"(gb)); \
            }                                                                            \
            asm volatile("cp.async.commit_group;");                                      \
        } while (0)

    PROJ_FILL(0, 0);
    int st = 0;
    for (int kt = 0; kt < DN; kt += 16) {
        if (kt + 16 < DN) {
            PROJ_FILL(st ^ 1, kt + 16);
            asm volatile("cp.async.wait_group 1;");
        } else {
            asm volatile("cp.async.wait_group 0;");
        }
        __syncthreads();

        #pragma unroll
        for (int k = 0; k < 16; k += 4) {
            unsigned long long b0[4], b1[4];
            #pragma unroll
            for (int j = 0; j < 4; j++) {
                ulonglong2 v = *(const ulonglong2*)&Bs[st][tx + j * 16][k ^ bsw];
                b0[j] = v.x; b1[j] = v.y;
            }
            #pragma unroll
            for (int i = 0; i < 8; i++) {
                ulonglong2 av = *(const ulonglong2*)&As[st][ty + i * 16][k];
                #pragma unroll
                for (int j = 0; j < 4; j++) {
                    acc[i][j] = fma2(av.x, b0[j], acc[i][j]);
                    acc[i][j] = fma2(av.y, b1[j], acc[i][j]);
                }
            }
        }
        __syncthreads();
        st ^= 1;
    }
    #undef PROJ_FILL

    float bsj[4];
    #pragma unroll
    for (int j = 0; j < 4; j++) {
        int n = n0 + tx + j * 16;
        bsj[j] = bih[n] + bhh[n];
    }
    #pragma unroll
    for (int i = 0; i < 8; i++) {
        int t = t0 + ty + i * 16;
        if (t < sent) {
            float* dst = &g_xg[((size_t)(dir * SN + t) * BN + b) * GN + n0 + tx];
            #pragma unroll
            for (int j = 0; j < 4; j++)
                dst[j * 16] = unpack_sum(acc[i][j]) + bsj[j];
        }
    }
}

// ---------------- K3: persistent LSTM, BOTH directions fused per block -------------
// 128 blocks, 1/SM. bg = blk>>5 (16 batches); u0 = (blk&31)*12 (12 hidden units
// = 48 gate rows per dir). Per step: f-phase then b-phase; each dir's barrier
// latency hides under the other dir's GEMV.
// GEMV per dir: 8 warps, ks=w>>1 (k-split 4, 96k), rg=w&1; lane bq=l>>3, rs=l&7;
// thread tile 3 rows x 4 batches (spacing 4) x 96 k, packed f32x2.
// Barriers: gid = bg*2+dir, 8 monotonic counters, 32 arrivals, absolute-gen.
__global__ void __launch_bounds__(REC_THREADS, 1) lstm_kernel(
    const float* __restrict__ Whhf, const float* __restrict__ Whhb,
    const float* __restrict__ bihf, const float* __restrict__ bhhf,
    const float* __restrict__ bihb, const float* __restrict__ bhhb,
    const float* __restrict__ h0, const float* __restrict__ c0)
{
    extern __shared__ float sm_[];
    float* wsf    = sm_;                          // 48*388 = 18624
    float* wsb    = sm_ + 18624;                  // 48*388 = 18624
    float* hsf    = sm_ + 37248;                  // 16*388 = 6208
    float* hsb    = sm_ + 37248 + 6208;           // 16*388 = 6208
    float* P      = sm_ + 37248 + 12416;          // 4*48*17 = 3264 (shared by phases)
    float* bias_f = P + 3264;                     // 48
    float* bias_b = bias_f + 48;                  // 48
    int*   sent_s = (int*)(bias_b + 48);          // 16

    int tid = threadIdx.x;
    int blk = blockIdx.x;
    int bg  = blk >> 5;           // batch group (16 batches)
    int u0  = (blk & 31) * 12;    // first hidden unit of slice

    // load both Whh slices
    for (int idx = tid; idx < 48 * HN; idx += REC_THREADS) {
        int r = idx / HN, k = idx % HN;
        int grow = (r / 12) * HN + u0 + (r % 12);
        wsf[r * 388 + k] = Whhf[(size_t)grow * HN + k];
        wsb[r * 388 + k] = Whhb[(size_t)grow * HN + k];
    }
    if (tid < 48) {
        int grow = (tid / 12) * HN + u0 + (tid % 12);
        bias_f[tid] = bihf[grow] + bhhf[grow];
        bias_b[tid] = bihb[grow] + bhhb[grow];
    }
    if (tid < 16) sent_s[tid] = g_sent[bg * 16 + tid];

    // cell ownership: tid < 192: lb = tid/12, u = tid%12
    bool cellv = (tid < 192);
    int lb = tid / 12, u = tid % 12;
    int gb = bg * 16 + lb;
    int gj = u0 + u;
    float cregf = 0.f, cregb = 0.f;
    if (cellv) {
        g_h[((0 * 2 + 0) * BN + gb) * HN + gj] = h0[((size_t)0 * BN + gb) * HN + gj];
        g_h[((1 * 2 + 0) * BN + gb) * HN + gj] = h0[((size_t)1 * BN + gb) * HN + gj];
        cregf = c0[((size_t)0 * BN + gb) * HN + gj];
        cregb = c0[((size_t)1 * BN + gb) * HN + gj];
    }

    // GEMV coords
    int w    = tid >> 5;
    int ks   = w >> 1;             // 0..3 (warp-uniform)
    int rg   = w & 1;              // 0..1 (warp-uniform)
    int lane = tid & 31;
    int bq   = lane >> 3;          // 0..3
    int rs   = lane & 7;           // 0..7
    int kbase = ks * 96;
    int r0 = rg * 24 + rs * 3;

    int gidf = bg * 2 + 0;
    int gidb = bg * 2 + 1;

    // absolute base generations (replay-safe)
    unsigned base_f = 0, base_b = 0;
    if (tid == 0) {
        base_f = ld_acquire(&g_bgen[gidf]);
        base_b = ld_acquire(&g_bgen[gidb]);
    }
    __syncthreads();

    // publish h0 for both dirs (arrive only; waits happen per-phase)
    if (tid == 0) {
        __threadfence();
        unsigned o = atom_add_acqrel(&g_bcnt[gidf], 1u);
        if (((o + 1) & 31u) == 0u) st_release_u32(&g_bgen[gidf], base_f + 1);
        o = atom_add_acqrel(&g_bcnt[gidb], 1u);
        if (((o + 1) & 31u) == 0u) st_release_u32(&g_bgen[gidb], base_b + 1);
    }

    for (int s = 0; s < SN; s++) {
        int p = s & 1;

        // =========================== PHASE macro ==============================
        #define LSTM_PHASE(DIR, WS, HSM, BIAS, GID, BASE, CREG, TT)                    \
        do {                                                                           \
            int t = (TT);                                                              \
            /* wait: h(s) of this dir published (round base+1+s) */                    \
            if (tid == 0) {                                                            \
                unsigned want = (BASE) + 1u + (unsigned)s;                             \
                while (ld_acquire(&g_bgen[GID]) != want) { }                           \
            }                                                                          \
            __syncthreads();                                                           \
            /* stage h slice: warp (ks,rg) stages batches rg*8..+8, k ks*96..+96 */    \
            {                                                                          \
                const float* hsrc = g_h + (size_t)(((DIR) * 2 + p) * BN + bg * 16) * HN; \
                _Pragma("unroll")                                                      \
                for (int c = 0; c < 6; c++) {                                          \
                    int idx = lane + c * 32;                                           \
                    int sb = rg * 8 + idx / 24;                                        \
                    int kk = (idx % 24) * 4;                                           \
                    unsigned sd = (unsigned)__cvta_generic_to_shared(&(HSM)[sb * 388 + kbase + kk]); \
                    const float* gsrc = hsrc + (size_t)sb * HN + kbase + kk;           \
                    asm volatile("cp.async.cg.shared.global [%0], [%1], 16;" :: "r"(sd), "l"(gsrc)); \
                }                                                                      \
                asm volatile("cp.async.commit_group;");                                \
            }                                                                          \
            /* prefetch xg (consumed in cell) */                                       \
            float xp[4];                                                               \
            if (cellv) {                                                               \
                const float* xb = &g_xg[((size_t)((DIR) * SN + t) * BN + gb) * GN + gj]; \
                _Pragma("unroll")                                                      \
                for (int g = 0; g < 4; g++) xp[g] = xb[g * HN];                        \
            }                                                                          \
            asm volatile("cp.async.wait_group 0;");                                    \
            asm volatile("bar.sync %0, 64;" :: "r"(1 + ks) : "memory");                \
            /* GEMV: 3 rows x 4 batches x 96 k */                                      \
            {                                                                          \
                const float* wr0 = &(WS)[(r0 + 0) * 388 + kbase];                      \
                const float* wr1 = &(WS)[(r0 + 1) * 388 + kbase];                      \
                const float* wr2 = &(WS)[(r0 + 2) * 388 + kbase];                      \
                unsigned long long acc[3][4];                                          \
                _Pragma("unroll")                                                      \
                for (int i = 0; i < 3; i++) {                                          \
                    acc[i][0] = 0ull; acc[i][1] = 0ull; acc[i][2] = 0ull; acc[i][3] = 0ull; \
                }                                                                      \
                _Pragma("unroll 4")                                                    \
                for (int kk = 0; kk < 96; kk += 4) {                                   \
                    ulonglong2 hv0 = *(const ulonglong2*)&(HSM)[(0 * 4 + bq) * 388 + kbase + kk]; \
                    ulonglong2 hv1 = *(const ulonglong2*)&(HSM)[(1 * 4 + bq) * 388 + kbase + kk]; \
                    ulonglong2 hv2 = *(const ulonglong2*)&(HSM)[(2 * 4 + bq) * 388 + kbase + kk]; \
                    ulonglong2 hv3 = *(const ulonglong2*)&(HSM)[(3 * 4 + bq) * 388 + kbase + kk]; \
                    ulonglong2 w0 = *(const ulonglong2*)(wr0 + kk);                    \
                    ulonglong2 w1 = *(const ulonglong2*)(wr1 + kk);                    \
                    ulonglong2 w2 = *(const ulonglong2*)(wr2 + kk);                    \
                    acc[0][0] = fma2(hv0.x, w0.x, acc[0][0]); acc[0][0] = fma2(hv0.y, w0.y, acc[0][0]); \
                    acc[0][1] = fma2(hv1.x, w0.x, acc[0][1]); acc[0][1] = fma2(hv1.y, w0.y, acc[0][1]); \
                    acc[0][2] = fma2(hv2.x, w0.x, acc[0][2]); acc[0][2] = fma2(hv2.y, w0.y, acc[0][2]); \
                    acc[0][3] = fma2(hv3.x, w0.x, acc[0][3]); acc[0][3] = fma2(hv3.y, w0.y, acc[0][3]); \
                    acc[1][0] = fma2(hv0.x, w1.x, acc[1][0]); acc[1][0] = fma2(hv0.y, w1.y, acc[1][0]); \
                    acc[1][1] = fma2(hv1.x, w1.x, acc[1][1]); acc[1][1] = fma2(hv1.y, w1.y, acc[1][1]); \
                    acc[1][2] = fma2(hv2.x, w1.x, acc[1][2]); acc[1][2] = fma2(hv2.y, w1.y, acc[1][2]); \
                    acc[1][3] = fma2(hv3.x, w1.x, acc[1][3]); acc[1][3] = fma2(hv3.y, w1.y, acc[1][3]); \
                    acc[2][0] = fma2(hv0.x, w2.x, acc[2][0]); acc[2][0] = fma2(hv0.y, w2.y, acc[2][0]); \
                    acc[2][1] = fma2(hv1.x, w2.x, acc[2][1]); acc[2][1] = fma2(hv1.y, w2.y, acc[2][1]); \
                    acc[2][2] = fma2(hv2.x, w2.x, acc[2][2]); acc[2][2] = fma2(hv2.y, w2.y, acc[2][2]); \
                    acc[2][3] = fma2(hv3.x, w2.x, acc[2][3]); acc[2][3] = fma2(hv3.y, w2.y, acc[2][3]); \
                }                                                                      \
                _Pragma("unroll")                                                      \
                for (int i = 0; i < 3; i++)                                            \
                    _Pragma("unroll")                                                  \
                    for (int j = 0; j < 4; j++)                                        \
                        P[(ks * 48 + r0 + i) * 17 + j * 4 + bq] = unpack_sum(acc[i][j]); \
            }                                                                          \
            __syncthreads();                                                           \
            /* cell update */                                                          \
            float hv = 0.f;                                                            \
            if (cellv) {                                                               \
                bool valid = (t < sent_s[lb]);                                         \
                float g4[4];                                                           \
                _Pragma("unroll")                                                      \
                for (int g = 0; g < 4; g++) {                                          \
                    int r = g * 12 + u;                                                \
                    float sum = P[(0 * 48 + r) * 17 + lb] + P[(1 * 48 + r) * 17 + lb]  \
                              + P[(2 * 48 + r) * 17 + lb] + P[(3 * 48 + r) * 17 + lb]; \
                    g4[g] = sum + (valid ? xp[g] : (BIAS)[r]);                         \
                }                                                                      \
                float ig = sig_fast(g4[0]), fg = sig_fast(g4[1]);                      \
                float cg = tanh_fast(g4[2]), og = sig_fast(g4[3]);                     \
                (CREG) = fg * (CREG) + ig * cg;                                        \
                hv = og * tanh_fast(CREG);                                             \
                g_h[(((DIR) * 2 + (p ^ 1)) * BN + gb) * HN + gj] = hv;                 \
            }                                                                          \
            __syncthreads();                                                           \
            /* arrive (publishes round base+2+s) */                                   \
            if (tid == 0) {                                                            \
                __threadfence();                                                       \
                unsigned o2 = atom_add_acqrel(&g_bcnt[GID], 1u);                       \
                if (((o2 + 1) & 31u) == 0u)                                            \
                    st_release_u32(&g_bgen[GID], (BASE) + 2u + (unsigned)s);           \
            }                                                                          \
            if (cellv)                                                                 \
                g_lstm[((size_t)gb * SN + t) * (2 * HN) + (DIR) * HN + gj] = hv;       \
        } while (0)
        // ======================================================================

        LSTM_PHASE(0, wsf, hsf, bias_f, gidf, base_f, cregf, s);
        LSTM_PHASE(1, wsb, hsb, bias_b, gidb, base_b, cregb, SN - 1 - s);

        #undef LSTM_PHASE
    }
}

// ---------------- K4: output linear (Wlin cached in smem, 16 rows/block) ----------
__global__ void __launch_bounds__(256) out_kernel(
    const float* __restrict__ Wlin, const float* __restrict__ blin,
    float* __restrict__ out)
{
    extern __shared__ float Wl[];   // 22*768 floats
    int tid = threadIdx.x;
    int lane = tid & 31, w = tid >> 5;
    for (int idx = tid; idx < TN * 768; idx += 256) Wl[idx] = Wlin[idx];
    __syncthreads();

    int base = blockIdx.x * 16;
    #pragma unroll
    for (int rr = 0; rr < 2; rr++) {
        int row = base + w * 2 + rr;
        const float* src = g_lstm + (size_t)row * 768;
        float rs[24];
        #pragma unroll
        for (int i = 0; i < 24; i++) rs[i] = src[lane + 32 * i];
        for (int o = 0; o < TN; o++) {
            const float* wr = &Wl[o * 768];
            float s = 0.f;
            #pragma unroll
            for (int i = 0; i < 24; i++) s += rs[i] * wr[lane + 32 * i];
            #pragma unroll
            for (int off = 16; off; off >>= 1) s += __shfl_down_sync(0xffffffffu, s, off);
            if (lane == 0) out[(size_t)row * TN + o] = s + blin[o];
        }
    }
}

// ---------------- launch -----------------------------------------------------------
extern "C" void kernel_launch(void* const* d_in, const int* in_sizes, int n_in,
                              void* d_out, int out_size) {
    const float* hs   = (const float*)d_in[0];
    const float* h0   = (const float*)d_in[1];
    const float* c0   = (const float*)d_in[2];
    const float* Wihf = (const float*)d_in[3];
    const float* Whhf = (const float*)d_in[4];
    const float* bihf = (const float*)d_in[5];
    const float* bhhf = (const float*)d_in[6];
    const float* Wihb = (const float*)d_in[7];
    const float* Whhb = (const float*)d_in[8];
    const float* bihb = (const float*)d_in[9];
    const float* bhhb = (const float*)d_in[10];
    const float* Wlin = (const float*)d_in[11];
    const float* blin = (const float*)d_in[12];
    const void*  sid  = d_in[13];
    const void*  msk  = d_in[14];

    meta_kernel<<<BN, 256>>>(sid, msk);
    gather_kernel<<<dim3(SN, BN), 192>>>(hs, sid);
    proj_kernel<<<dim3(GN / 64, SN / 128, 2 * BN), 256>>>(Wihf, Wihb, bihf, bhhf, bihb, bhhb);

    // smem: 2*18624 + 2*6208 + 3264 + 48 + 48 + 16 floats = 53,040 fl = 212,160 B
    const int rec_smem = (2 * 18624 + 2 * 6208 + 3264 + 48 + 48 + 16) * 4;
    cudaFuncSetAttribute(lstm_kernel, cudaFuncAttributeMaxDynamicSharedMemorySize, rec_smem);
    lstm_kernel<<<NBLK_REC, REC_THREADS, rec_smem>>>(Whhf, Whhb, bihf, bhhf, bihb, bhhb, h0, c0);

    const int out_smem = TN * 768 * 4;
    cudaFuncSetAttribute(out_kernel, cudaFuncAttributeMaxDynamicSharedMemorySize, out_smem);
    out_kernel<<<(BN * SN) / 16, 256, out_smem>>>(Wlin, blin, (float*)d_out);
}